// round 7
// baseline (speedup 1.0000x reference)
#include <cuda_runtime.h>
#include <math.h>

#define NCLUST 196
#define DIM 256
#define NROWS 262144
#define TEMP_INV 2.0f        // 1/TEMPERATURE
#define EPSV 1e-12f

// -------- scratch (device globals; no allocation allowed) --------
__device__ float g_sums[2][NCLUST * DIM];       // [q,k] raw segment sums
struct Meta {
    int counts[NCLUST];
    int cursor[NCLUST];
    int barrier;
    int done;
    float loss_sum;
};
__device__ Meta g_m;                            // zeroed by one memset
__device__ unsigned g_pack[NROWS];              // (label<<18) | row

// -------- 1. fused hist + scan + scatter. grid 512 x 256 (co-resident) ----
// Phase 1: per-block smem histogram -> global counts. Grid barrier.
// Phase 2: every block scans final counts, reserves base, writes pack.
__global__ void __launch_bounds__(256) k_prep(const int* __restrict__ labels) {
    __shared__ int s_hist[NCLUST];
    __shared__ int s_base[NCLUST];
    __shared__ int s_scan[256];
    const int t = threadIdx.x;

    for (int i = t; i < NCLUST; i += 256) s_hist[i] = 0;
    __syncthreads();

    const int r0 = blockIdx.x * 512;
    int labs[2], rk[2];
#pragma unroll
    for (int u = 0; u < 2; u++) labs[u] = labels[r0 + u * 256 + t];
#pragma unroll
    for (int u = 0; u < 2; u++) rk[u] = atomicAdd(&s_hist[labs[u]], 1);
    __syncthreads();

    if (t < NCLUST && s_hist[t]) atomicAdd(&g_m.counts[t], s_hist[t]);
    __threadfence();
    __syncthreads();

    // software grid barrier (all 512 blocks are co-resident)
    if (t == 0) {
        atomicAdd(&g_m.barrier, 1);
        while (atomicAdd(&g_m.barrier, 0) < (int)gridDim.x) { }
    }
    __syncthreads();

    // counts are final now; per-block exclusive scan (redundant but cheap)
    int cv = (t < NCLUST) ? atomicAdd(&g_m.counts[t], 0) : 0;
    s_scan[t] = cv;
    __syncthreads();
#pragma unroll
    for (int off = 1; off < 256; off <<= 1) {
        int add = (t >= off) ? s_scan[t - off] : 0;
        __syncthreads();
        s_scan[t] += add;
        __syncthreads();
    }
    if (t < NCLUST) {
        int h = s_hist[t];
        if (h) s_base[t] = (s_scan[t] - cv) + atomicAdd(&g_m.cursor[t], h);
    }
    __syncthreads();
#pragma unroll
    for (int u = 0; u < 2; u++) {
        int c = labs[u];
        int p = s_base[c] + rk[u];
        g_pack[p] = ((unsigned)c << 18) | (unsigned)(r0 + u * 256 + t);
    }
}

// -------- 2. segment sums over label-sorted rows (hot kernel) --------
__global__ void __launch_bounds__(256, 5) k_segsum(const float* __restrict__ xq,
                                                   const float* __restrict__ xk) {
    const float* __restrict__ x = blockIdx.y ? xk : xq;
    float* sums = &g_sums[blockIdx.y][0];
    const int t = threadIdx.x;
    const int dq = (t & 63) * 4;      // dim-quad base
    const int sub = t >> 6;           // 0..3
    const int start = blockIdx.x * 256;

    int cur = (int)(g_pack[start + sub] >> 18);
    float4 acc = make_float4(0.f, 0.f, 0.f, 0.f);

    for (int it = 0; it < 64; it += 8) {
        unsigned pk[8];
        float4 v[8];
#pragma unroll
        for (int u = 0; u < 8; u++)
            pk[u] = g_pack[start + sub + (it + u) * 4];
#pragma unroll
        for (int u = 0; u < 8; u++)
            v[u] = __ldcs((const float4*)&x[(size_t)(pk[u] & 0x3FFFFu) * DIM + dq]);
#pragma unroll
        for (int u = 0; u < 8; u++) {
            int lb = (int)(pk[u] >> 18);
            if (lb != cur) {
                float* dst = &sums[cur * DIM + dq];
                atomicAdd(dst + 0, acc.x);
                atomicAdd(dst + 1, acc.y);
                atomicAdd(dst + 2, acc.z);
                atomicAdd(dst + 3, acc.w);
                acc = make_float4(0.f, 0.f, 0.f, 0.f);
                cur = lb;
            }
            acc.x += v[u].x;
            acc.y += v[u].y;
            acc.z += v[u].z;
            acc.w += v[u].w;
        }
    }
    float* dst = &sums[cur * DIM + dq];
    atomicAdd(dst + 0, acc.x);
    atomicAdd(dst + 1, acc.y);
    atomicAdd(dst + 2, acc.z);
    atomicAdd(dst + 3, acc.w);
}

// -------- 3. loss on RAW sums (normalization folded into scaling) ------
// dot(c_i,c_j) = dot(s_i,s_j) * inv_i * inv_j, inv = 1/max(||s||,eps).
// 2 rows per block, grid 98; norms come free in the dot pass; ticket final.
__global__ void k_loss(float* out) {
    const int i0 = blockIdx.x * 2;
    const int i1 = i0 + 1;
    const int tid = threadIdx.x;
    const int lane = tid & 31, w = tid >> 5;
    __shared__ float s_q0[DIM], s_q1[DIM];
    __shared__ float s_row0[NCLUST], s_row1[NCLUST];
    __shared__ float s_n[NCLUST];           // raw normsq of q rows
    __shared__ float s_dkraw[2], s_nk[2];   // raw k-diag dot, k normsq
    __shared__ float s_r0[8], s_r1[8];
    __shared__ float s_mx0, s_mx1, s_sum0, s_sum1;

    const float* sq = &g_sums[0][0];
    const float* sk = &g_sums[1][0];

    s_q0[tid] = sq[i0 * DIM + tid];
    s_q1[tid] = sq[i1 * DIM + tid];
    __syncthreads();

    const float4* q0v = (const float4*)s_q0;
    const float4* q1v = (const float4*)s_q1;
    float4 a0 = q0v[lane], b0 = q0v[32 + lane];
    float4 a1 = q1v[lane], b1 = q1v[32 + lane];

    // warps cover j = w, w+8, ...: dots with i0,i1 and normsq of row j
    for (int j = w; j < NCLUST; j += 8) {
        const float4* vj = (const float4*)&sq[j * DIM];
        float4 va = vj[lane], vb = vj[32 + lane];
        float p0 = va.x * a0.x + va.y * a0.y + va.z * a0.z + va.w * a0.w
                 + vb.x * b0.x + vb.y * b0.y + vb.z * b0.z + vb.w * b0.w;
        float p1 = va.x * a1.x + va.y * a1.y + va.z * a1.z + va.w * a1.w
                 + vb.x * b1.x + vb.y * b1.y + vb.z * b1.z + vb.w * b1.w;
        float nn = va.x * va.x + va.y * va.y + va.z * va.z + va.w * va.w
                 + vb.x * vb.x + vb.y * vb.y + vb.z * vb.z + vb.w * vb.w;
#pragma unroll
        for (int off = 16; off > 0; off >>= 1) {
            p0 += __shfl_xor_sync(0xFFFFFFFFu, p0, off);
            p1 += __shfl_xor_sync(0xFFFFFFFFu, p1, off);
            nn += __shfl_xor_sync(0xFFFFFFFFu, nn, off);
        }
        if (lane == 0) {
            s_row0[j] = p0;
            s_row1[j] = p1;
            s_n[j] = nn;
        }
    }
    // diagonals vs k: warp 0 -> i0, warp 1 -> i1 (raw dot + k normsq)
    if (w < 2) {
        const float4* vj = (const float4*)&sk[(w ? i1 : i0) * DIM];
        float4 va = vj[lane], vb = vj[32 + lane];
        float4 ca = w ? a1 : a0, cb = w ? b1 : b0;
        float p = va.x * ca.x + va.y * ca.y + va.z * ca.z + va.w * ca.w
                + vb.x * cb.x + vb.y * cb.y + vb.z * cb.z + vb.w * cb.w;
        float nn = va.x * va.x + va.y * va.y + va.z * va.z + va.w * va.w
                 + vb.x * vb.x + vb.y * vb.y + vb.z * vb.z + vb.w * vb.w;
#pragma unroll
        for (int off = 16; off > 0; off >>= 1) {
            p += __shfl_xor_sync(0xFFFFFFFFu, p, off);
            nn += __shfl_xor_sync(0xFFFFFFFFu, nn, off);
        }
        if (lane == 0) { s_dkraw[w] = p; s_nk[w] = nn; }
    }
    __syncthreads();

    // scale rows + mask: diag <- d_k; empty columns <- -10
    const float inv0 = 1.0f / fmaxf(sqrtf(s_n[i0]), EPSV);
    const float inv1 = 1.0f / fmaxf(sqrtf(s_n[i1]), EPSV);
    if (tid < NCLUST) {
        float invj = 1.0f / fmaxf(sqrtf(s_n[tid]), EPSV);
        float r0, r1;
        if (tid == i0)
            r0 = s_dkraw[0] * inv0 / fmaxf(sqrtf(s_nk[0]), EPSV) * TEMP_INV;
        else
            r0 = s_row0[tid] * inv0 * invj * TEMP_INV;
        if (tid == i1)
            r1 = s_dkraw[1] * inv1 / fmaxf(sqrtf(s_nk[1]), EPSV) * TEMP_INV;
        else
            r1 = s_row1[tid] * inv1 * invj * TEMP_INV;
        if (g_m.counts[tid] == 0) { r0 = -10.0f; r1 = -10.0f; }
        s_row0[tid] = r0;
        s_row1[tid] = r1;
    }
    __syncthreads();

    // joint max reduce
    float v0 = (tid < NCLUST) ? s_row0[tid] : -1e30f;
    float v1 = (tid < NCLUST) ? s_row1[tid] : -1e30f;
#pragma unroll
    for (int off = 16; off > 0; off >>= 1) {
        v0 = fmaxf(v0, __shfl_xor_sync(0xFFFFFFFFu, v0, off));
        v1 = fmaxf(v1, __shfl_xor_sync(0xFFFFFFFFu, v1, off));
    }
    if (lane == 0) { s_r0[w] = v0; s_r1[w] = v1; }
    __syncthreads();
    if (tid == 0) {
        float m0 = s_r0[0], m1 = s_r1[0];
        for (int k = 1; k < 8; k++) {
            m0 = fmaxf(m0, s_r0[k]);
            m1 = fmaxf(m1, s_r1[k]);
        }
        s_mx0 = m0; s_mx1 = m1;
    }
    __syncthreads();
    float mx0 = s_mx0, mx1 = s_mx1;

    float e0 = (tid < NCLUST) ? __expf(s_row0[tid] - mx0) : 0.0f;
    float e1 = (tid < NCLUST) ? __expf(s_row1[tid] - mx1) : 0.0f;
#pragma unroll
    for (int off = 16; off > 0; off >>= 1) {
        e0 += __shfl_xor_sync(0xFFFFFFFFu, e0, off);
        e1 += __shfl_xor_sync(0xFFFFFFFFu, e1, off);
    }
    if (lane == 0) { s_r0[w] = e0; s_r1[w] = e1; }
    __syncthreads();
    if (tid == 0) {
        float t0 = 0.f, t1 = 0.f;
        for (int k = 0; k < 8; k++) { t0 += s_r0[k]; t1 += s_r1[k]; }
        s_sum0 = t0; s_sum1 = t1;
    }
    __syncthreads();

    if (tid == 0) {
        float loss = 0.0f;
        if (g_m.counts[i0] != 0) loss += -s_row0[i0] + mx0 + logf(s_sum0);
        if (g_m.counts[i1] != 0) loss += -s_row1[i1] + mx1 + logf(s_sum1);
        if (loss != 0.0f) atomicAdd(&g_m.loss_sum, loss);
        __threadfence();
        int ticket = atomicAdd(&g_m.done, 1);
        if (ticket == NCLUST / 2 - 1) {
            float tot = atomicAdd(&g_m.loss_sum, 0.0f);
            int nz = 0;
            for (int k = 0; k < NCLUST; k++)
                if (g_m.counts[k] == 0) nz++;
            out[0] = tot / ((float)NCLUST - (float)nz);
        }
    }
}

extern "C" void kernel_launch(void* const* d_in, const int* in_sizes, int n_in,
                              void* d_out, int out_size) {
    const float* im_q = (const float*)d_in[0];
    const float* im_k = (const float*)d_in[1];
    const int* labels = (const int*)d_in[2];
    float* out = (float*)d_out;

    void *p_sums = 0, *p_meta = 0;
    cudaGetSymbolAddress(&p_sums, g_sums);
    cudaGetSymbolAddress(&p_meta, g_m);
    cudaMemsetAsync(p_sums, 0, sizeof(float) * 2 * NCLUST * DIM);
    cudaMemsetAsync(p_meta, 0, sizeof(Meta));

    k_prep<<<512, 256>>>(labels);
    dim3 gs(NROWS / 256, 2);
    k_segsum<<<gs, 256>>>(im_q, im_k);
    k_loss<<<NCLUST / 2, 256>>>(out);
}

// round 8
// speedup vs baseline: 1.0532x; 1.0532x over previous
#include <cuda_runtime.h>
#include <math.h>

#define NCLUST 196
#define DIM 256
#define NROWS 262144
#define TEMP_INV 2.0f        // 1/TEMPERATURE
#define EPSV 1e-12f

// -------- scratch (device globals; no allocation allowed) --------
__device__ float g_sums[2][NCLUST * DIM];       // [q,k] raw segment sums
struct Meta {
    int counts[NCLUST];
    int cursor[NCLUST];
    int done;
    float loss_sum;
};
__device__ Meta g_m;                            // zeroed by one memset
__device__ unsigned g_pack[NROWS];              // (label<<18) | row

// -------- 1. histogram. 64 blocks (minimize contended global atomics) ----
__global__ void k_hist(const int* __restrict__ labels) {
    __shared__ int s_cnt[NCLUST];
    for (int i = threadIdx.x; i < NCLUST; i += blockDim.x) s_cnt[i] = 0;
    __syncthreads();
    const int4* l4 = (const int4*)labels;
    for (int r = blockIdx.x * blockDim.x + threadIdx.x; r < NROWS / 4;
         r += gridDim.x * blockDim.x) {
        int4 v = l4[r];
        atomicAdd(&s_cnt[v.x], 1);
        atomicAdd(&s_cnt[v.y], 1);
        atomicAdd(&s_cnt[v.z], 1);
        atomicAdd(&s_cnt[v.w], 1);
    }
    __syncthreads();
    for (int i = threadIdx.x; i < NCLUST; i += blockDim.x)
        if (s_cnt[i]) atomicAdd(&g_m.counts[i], s_cnt[i]);
}

// -------- 2. scatter (scan fused). 128 blocks x 256, 2048 rows/block ----
__global__ void __launch_bounds__(256) k_scatter(const int* __restrict__ labels) {
    __shared__ int s_hist[NCLUST];
    __shared__ int s_base[NCLUST];
    __shared__ int s_scan[256];
    const int t = threadIdx.x;

    // per-block exclusive scan of final global counts
    int cv = (t < NCLUST) ? g_m.counts[t] : 0;
    s_scan[t] = cv;
    for (int i = t; i < NCLUST; i += 256) s_hist[i] = 0;
    __syncthreads();
#pragma unroll
    for (int off = 1; off < 256; off <<= 1) {
        int add = (t >= off) ? s_scan[t - off] : 0;
        __syncthreads();
        s_scan[t] += add;
        __syncthreads();
    }

    const int r0 = blockIdx.x * 2048;
    int labs[8], rk[8];
#pragma unroll
    for (int u = 0; u < 8; u++) labs[u] = labels[r0 + u * 256 + t];
#pragma unroll
    for (int u = 0; u < 8; u++) rk[u] = atomicAdd(&s_hist[labs[u]], 1);
    __syncthreads();
    if (t < NCLUST) {
        int h = s_hist[t];
        if (h) s_base[t] = (s_scan[t] - cv) + atomicAdd(&g_m.cursor[t], h);
    }
    __syncthreads();
#pragma unroll
    for (int u = 0; u < 8; u++) {
        int c = labs[u];
        int p = s_base[c] + rk[u];
        g_pack[p] = ((unsigned)c << 18) | (unsigned)(r0 + u * 256 + t);
    }
}

// -------- 3. segment sums over label-sorted rows (hot kernel) --------
__global__ void __launch_bounds__(256, 5) k_segsum(const float* __restrict__ xq,
                                                   const float* __restrict__ xk) {
    const float* __restrict__ x = blockIdx.y ? xk : xq;
    float* sums = &g_sums[blockIdx.y][0];
    const int t = threadIdx.x;
    const int dq = (t & 63) * 4;      // dim-quad base
    const int sub = t >> 6;           // 0..3
    const int start = blockIdx.x * 256;

    int cur = (int)(g_pack[start + sub] >> 18);
    float4 acc = make_float4(0.f, 0.f, 0.f, 0.f);

    for (int it = 0; it < 64; it += 8) {
        unsigned pk[8];
        float4 v[8];
#pragma unroll
        for (int u = 0; u < 8; u++)
            pk[u] = g_pack[start + sub + (it + u) * 4];
#pragma unroll
        for (int u = 0; u < 8; u++)
            v[u] = __ldcs((const float4*)&x[(size_t)(pk[u] & 0x3FFFFu) * DIM + dq]);
#pragma unroll
        for (int u = 0; u < 8; u++) {
            int lb = (int)(pk[u] >> 18);
            if (lb != cur) {
                float* dst = &sums[cur * DIM + dq];
                atomicAdd(dst + 0, acc.x);
                atomicAdd(dst + 1, acc.y);
                atomicAdd(dst + 2, acc.z);
                atomicAdd(dst + 3, acc.w);
                acc = make_float4(0.f, 0.f, 0.f, 0.f);
                cur = lb;
            }
            acc.x += v[u].x;
            acc.y += v[u].y;
            acc.z += v[u].z;
            acc.w += v[u].w;
        }
    }
    float* dst = &sums[cur * DIM + dq];
    atomicAdd(dst + 0, acc.x);
    atomicAdd(dst + 1, acc.y);
    atomicAdd(dst + 2, acc.z);
    atomicAdd(dst + 3, acc.w);
}

// -------- 4. loss on RAW sums (normalization folded into scaling) ------
// dot(c_i,c_j) = dot(s_i,s_j) * inv_i * inv_j, inv = 1/max(||s||,eps).
// 2 rows per block, grid 98; norms free in the dot pass; ticket final.
__global__ void k_loss(float* out) {
    const int i0 = blockIdx.x * 2;
    const int i1 = i0 + 1;
    const int tid = threadIdx.x;
    const int lane = tid & 31, w = tid >> 5;
    __shared__ float s_q0[DIM], s_q1[DIM];
    __shared__ float s_row0[NCLUST], s_row1[NCLUST];
    __shared__ float s_n[NCLUST];           // raw normsq of q rows
    __shared__ float s_dkraw[2], s_nk[2];   // raw k-diag dot, k normsq
    __shared__ float s_r0[8], s_r1[8];
    __shared__ float s_mx0, s_mx1, s_sum0, s_sum1;

    const float* sq = &g_sums[0][0];
    const float* sk = &g_sums[1][0];

    s_q0[tid] = sq[i0 * DIM + tid];
    s_q1[tid] = sq[i1 * DIM + tid];
    __syncthreads();

    const float4* q0v = (const float4*)s_q0;
    const float4* q1v = (const float4*)s_q1;
    float4 a0 = q0v[lane], b0 = q0v[32 + lane];
    float4 a1 = q1v[lane], b1 = q1v[32 + lane];

    for (int j = w; j < NCLUST; j += 8) {
        const float4* vj = (const float4*)&sq[j * DIM];
        float4 va = vj[lane], vb = vj[32 + lane];
        float p0 = va.x * a0.x + va.y * a0.y + va.z * a0.z + va.w * a0.w
                 + vb.x * b0.x + vb.y * b0.y + vb.z * b0.z + vb.w * b0.w;
        float p1 = va.x * a1.x + va.y * a1.y + va.z * a1.z + va.w * a1.w
                 + vb.x * b1.x + vb.y * b1.y + vb.z * b1.z + vb.w * b1.w;
        float nn = va.x * va.x + va.y * va.y + va.z * va.z + va.w * va.w
                 + vb.x * vb.x + vb.y * vb.y + vb.z * vb.z + vb.w * vb.w;
#pragma unroll
        for (int off = 16; off > 0; off >>= 1) {
            p0 += __shfl_xor_sync(0xFFFFFFFFu, p0, off);
            p1 += __shfl_xor_sync(0xFFFFFFFFu, p1, off);
            nn += __shfl_xor_sync(0xFFFFFFFFu, nn, off);
        }
        if (lane == 0) {
            s_row0[j] = p0;
            s_row1[j] = p1;
            s_n[j] = nn;
        }
    }
    if (w < 2) {
        const float4* vj = (const float4*)&sk[(w ? i1 : i0) * DIM];
        float4 va = vj[lane], vb = vj[32 + lane];
        float4 ca = w ? a1 : a0, cb = w ? b1 : b0;
        float p = va.x * ca.x + va.y * ca.y + va.z * ca.z + va.w * ca.w
                + vb.x * cb.x + vb.y * cb.y + vb.z * cb.z + vb.w * cb.w;
        float nn = va.x * va.x + va.y * va.y + va.z * va.z + va.w * va.w
                 + vb.x * vb.x + vb.y * vb.y + vb.z * vb.z + vb.w * vb.w;
#pragma unroll
        for (int off = 16; off > 0; off >>= 1) {
            p += __shfl_xor_sync(0xFFFFFFFFu, p, off);
            nn += __shfl_xor_sync(0xFFFFFFFFu, nn, off);
        }
        if (lane == 0) { s_dkraw[w] = p; s_nk[w] = nn; }
    }
    __syncthreads();

    const float inv0 = 1.0f / fmaxf(sqrtf(s_n[i0]), EPSV);
    const float inv1 = 1.0f / fmaxf(sqrtf(s_n[i1]), EPSV);
    if (tid < NCLUST) {
        float invj = 1.0f / fmaxf(sqrtf(s_n[tid]), EPSV);
        float r0, r1;
        if (tid == i0)
            r0 = s_dkraw[0] * inv0 / fmaxf(sqrtf(s_nk[0]), EPSV) * TEMP_INV;
        else
            r0 = s_row0[tid] * inv0 * invj * TEMP_INV;
        if (tid == i1)
            r1 = s_dkraw[1] * inv1 / fmaxf(sqrtf(s_nk[1]), EPSV) * TEMP_INV;
        else
            r1 = s_row1[tid] * inv1 * invj * TEMP_INV;
        if (g_m.counts[tid] == 0) { r0 = -10.0f; r1 = -10.0f; }
        s_row0[tid] = r0;
        s_row1[tid] = r1;
    }
    __syncthreads();

    float v0 = (tid < NCLUST) ? s_row0[tid] : -1e30f;
    float v1 = (tid < NCLUST) ? s_row1[tid] : -1e30f;
#pragma unroll
    for (int off = 16; off > 0; off >>= 1) {
        v0 = fmaxf(v0, __shfl_xor_sync(0xFFFFFFFFu, v0, off));
        v1 = fmaxf(v1, __shfl_xor_sync(0xFFFFFFFFu, v1, off));
    }
    if (lane == 0) { s_r0[w] = v0; s_r1[w] = v1; }
    __syncthreads();
    if (tid == 0) {
        float m0 = s_r0[0], m1 = s_r1[0];
        for (int k = 1; k < 8; k++) {
            m0 = fmaxf(m0, s_r0[k]);
            m1 = fmaxf(m1, s_r1[k]);
        }
        s_mx0 = m0; s_mx1 = m1;
    }
    __syncthreads();
    float mx0 = s_mx0, mx1 = s_mx1;

    float e0 = (tid < NCLUST) ? __expf(s_row0[tid] - mx0) : 0.0f;
    float e1 = (tid < NCLUST) ? __expf(s_row1[tid] - mx1) : 0.0f;
#pragma unroll
    for (int off = 16; off > 0; off >>= 1) {
        e0 += __shfl_xor_sync(0xFFFFFFFFu, e0, off);
        e1 += __shfl_xor_sync(0xFFFFFFFFu, e1, off);
    }
    if (lane == 0) { s_r0[w] = e0; s_r1[w] = e1; }
    __syncthreads();
    if (tid == 0) {
        float t0 = 0.f, t1 = 0.f;
        for (int k = 0; k < 8; k++) { t0 += s_r0[k]; t1 += s_r1[k]; }
        s_sum0 = t0; s_sum1 = t1;
    }
    __syncthreads();

    if (tid == 0) {
        float loss = 0.0f;
        if (g_m.counts[i0] != 0) loss += -s_row0[i0] + mx0 + logf(s_sum0);
        if (g_m.counts[i1] != 0) loss += -s_row1[i1] + mx1 + logf(s_sum1);
        if (loss != 0.0f) atomicAdd(&g_m.loss_sum, loss);
        __threadfence();
        int ticket = atomicAdd(&g_m.done, 1);
        if (ticket == NCLUST / 2 - 1) {
            float tot = atomicAdd(&g_m.loss_sum, 0.0f);
            int nz = 0;
            for (int k = 0; k < NCLUST; k++)
                if (g_m.counts[k] == 0) nz++;
            out[0] = tot / ((float)NCLUST - (float)nz);
        }
    }
}

extern "C" void kernel_launch(void* const* d_in, const int* in_sizes, int n_in,
                              void* d_out, int out_size) {
    const float* im_q = (const float*)d_in[0];
    const float* im_k = (const float*)d_in[1];
    const int* labels = (const int*)d_in[2];
    float* out = (float*)d_out;

    void *p_sums = 0, *p_meta = 0;
    cudaGetSymbolAddress(&p_sums, g_sums);
    cudaGetSymbolAddress(&p_meta, g_m);
    cudaMemsetAsync(p_sums, 0, sizeof(float) * 2 * NCLUST * DIM);
    cudaMemsetAsync(p_meta, 0, sizeof(Meta));

    k_hist<<<64, 256>>>(labels);
    k_scatter<<<128, 256>>>(labels);
    dim3 gs(NROWS / 256, 2);
    k_segsum<<<gs, 256>>>(im_q, im_k);
    k_loss<<<NCLUST / 2, 256>>>(out);
}